// round 8
// baseline (speedup 1.0000x reference)
#include <cuda_runtime.h>
#include <math.h>

// ---------------------------------------------------------------------------
// GRELEN: gumbel-softmax adjacency + 2x diffusion-GCN GRU cell
// B=16, N=1024, U=64, K=2  (reference stacks [x, Ax, Ax] due to its loop quirk)
// R8 (= R7 resubmit after infra failure): 3xTF32 weight GEMMs w/ in-register
//     W split (smem fits), fp32 Z, algebraic adjacency.
// ---------------------------------------------------------------------------

namespace {
constexpr int Bb   = 16;
constexpr int Nn   = 1024;
constexpr int Uu   = 64;
constexpr int DU   = 128;   // 2U
constexpr int DIN  = 384;   // 2U*(K+1)
constexpr int Mrows = Bb * Nn;       // 16384
constexpr float EPSc = 1e-10f;
}

// ------------------------------ scratch ------------------------------------
__device__ float g_adj[(size_t)Bb * Nn * Nn];   // 64 MB (tf32-rounded)
__device__ float g_rowsum[Mrows];
__device__ float g_cpart[4][Mrows];
__device__ float g_dinv0[Mrows];
__device__ float g_dinv1[Mrows];
__device__ float g_X1 [Mrows * DU];             // [xin | h] tf32-rounded (gemm operand)
__device__ float g_XRH[Mrows * Uu];             // r*h tf32-rounded (gemm operand)
__device__ float g_Ug [Mrows * Uu];
__device__ float g_Z  [(size_t)Mrows * DIN];    // FULL fp32 shared Z1->Z2 staging
__device__ float g_W1cat[DU * DIN];             // full fp32 folded weights
__device__ float g_Wccat[Uu * DIN];
__device__ float g_b1s[DU];
__device__ float g_bcs[Uu];

__device__ __forceinline__ float4 ld4(const float* p) { return *reinterpret_cast<const float4*>(p); }
__device__ __forceinline__ void   st4(float* p, float4 v) { *reinterpret_cast<float4*>(p) = v; }
__device__ __forceinline__ float sigm(float x) { return 1.0f / (1.0f + expf(-x)); }

__device__ __forceinline__ float to_tf32(float x) {
    unsigned u;
    asm("cvt.rna.tf32.f32 %0, %1;" : "=r"(u) : "f"(x));
    return __uint_as_float(u);
}
__device__ __forceinline__ float4 to_tf32_4(float4 v) {
    v.x = to_tf32(v.x); v.y = to_tf32(v.y); v.z = to_tf32(v.z); v.w = to_tf32(v.w);
    return v;
}

__device__ __forceinline__ void cpasync16(float* dst_smem, const float* src) {
    unsigned d = (unsigned)__cvta_generic_to_shared(dst_smem);
    asm volatile("cp.async.cg.shared.global [%0], [%1], 16;\n" :: "r"(d), "l"(src));
}
__device__ __forceinline__ void cp_commit() {
    asm volatile("cp.async.commit_group;\n" ::: "memory");
}
template <int N>
__device__ __forceinline__ void cp_wait() {
    asm volatile("cp.async.wait_group %0;\n" :: "n"(N) : "memory");
}

__device__ __forceinline__ void mma_tf32(float (&d)[4], const float a0, const float a1,
                                         const float a2, const float a3,
                                         const float b0, const float b1) {
    asm volatile(
        "mma.sync.aligned.m16n8k8.row.col.f32.tf32.tf32.f32 "
        "{%0,%1,%2,%3}, {%4,%5,%6,%7}, {%8,%9}, {%0,%1,%2,%3};\n"
        : "+f"(d[0]), "+f"(d[1]), "+f"(d[2]), "+f"(d[3])
        : "r"(__float_as_uint(a0)), "r"(__float_as_uint(a1)),
          "r"(__float_as_uint(a2)), "r"(__float_as_uint(a3)),
          "r"(__float_as_uint(b0)), "r"(__float_as_uint(b1)));
}

// ------------------------------ weight folding (full fp32) -----------------
__global__ void k_prep(const float* __restrict__ W0, const float* __restrict__ b0,
                       const float* __restrict__ W1, const float* __restrict__ b1,
                       const float* __restrict__ Wc0, const float* __restrict__ bc0,
                       const float* __restrict__ Wc1, const float* __restrict__ bc1) {
    int t = blockIdx.x * blockDim.x + threadIdx.x;
    int stride = gridDim.x * blockDim.x;
    for (int idx = t; idx < DU * DIN; idx += stride) {
        int o = idx / DIN, k = idx % DIN;
        float v;
        if (k < DU)            v = W0[o*DIN + 3*k]     + W1[o*DIN + 3*k];
        else if (k < 2*DU)   { int f = k - DU;   v = W0[o*DIN + 3*f+1] + W0[o*DIN + 3*f+2]; }
        else                 { int f = k - 2*DU; v = W1[o*DIN + 3*f+1] + W1[o*DIN + 3*f+2]; }
        g_W1cat[idx] = v;
    }
    for (int idx = t; idx < Uu * DIN; idx += stride) {
        int o = idx / DIN, k = idx % DIN;
        float v;
        if (k < DU)            v = Wc0[o*DIN + 3*k]     + Wc1[o*DIN + 3*k];
        else if (k < 2*DU)   { int f = k - DU;   v = Wc0[o*DIN + 3*f+1] + Wc0[o*DIN + 3*f+2]; }
        else                 { int f = k - 2*DU; v = Wc1[o*DIN + 3*f+1] + Wc1[o*DIN + 3*f+2]; }
        g_Wccat[idx] = v;
    }
    if (t < DU) g_b1s[t] = b0[t] + b1[t];
    if (t < Uu) g_bcs[t] = bc0[t] + bc1[t];
}

// ------------------------------ adjacency + row sums -----------------------
// p = 1 / (1 + e^{2(l1-l0)} (t0/t1)^2),  t_i = eps - log(u_i+eps)
__global__ void k_adj(const float4* __restrict__ logits4, const float4* __restrict__ un4) {
    int b = blockIdx.y, i = blockIdx.x, t = threadIdx.x;
    size_t base4 = (size_t)(b * Nn + i) * (Nn / 2);
    float2* adj2 = reinterpret_cast<float2*>(g_adj + (size_t)(b * Nn + i) * Nn);
    float s = 0.0f;
    #pragma unroll
    for (int j = t; j < Nn / 2; j += 256) {
        float4 l = logits4[base4 + j];
        float4 u = un4[base4 + j];
        float t0a = EPSc - __logf(u.x + EPSc), t1a = EPSc - __logf(u.y + EPSc);
        float t0b = EPSc - __logf(u.z + EPSc), t1b = EPSc - __logf(u.w + EPSc);
        float ra = __fdividef(t0a, t1a);
        float rb = __fdividef(t0b, t1b);
        float wa = __expf(2.0f * (l.y - l.x)) * ra * ra;
        float wb = __expf(2.0f * (l.w - l.z)) * rb * rb;
        float pa = to_tf32(__fdividef(1.0f, 1.0f + wa));
        float pb = to_tf32(__fdividef(1.0f, 1.0f + wb));
        adj2[j] = make_float2(pa, pb);
        s += pa + pb;
    }
    #pragma unroll
    for (int o = 16; o; o >>= 1) s += __shfl_down_sync(0xffffffffu, s, o);
    __shared__ float red[8];
    if ((t & 31) == 0) red[t >> 5] = s;
    __syncthreads();
    if (t == 0) {
        float tot = 0.0f;
        #pragma unroll
        for (int w = 0; w < 8; w++) tot += red[w];
        g_rowsum[b * Nn + i] = tot;
    }
}

// ------------------------------ column sums (4 partials) -------------------
__global__ void k_colsum_part() {
    int b = blockIdx.y, q = blockIdx.z;
    int j = blockIdx.x * 256 + threadIdx.x;
    size_t base = (size_t)b * Nn * Nn + (size_t)q * (Nn / 4) * Nn + j;
    float s = 0.0f;
    #pragma unroll 8
    for (int i = 0; i < Nn / 4; i++) s += g_adj[base + (size_t)i * Nn];
    g_cpart[q][b * Nn + j] = s;
}

__global__ void k_dinv() {
    int i = blockIdx.x * 256 + threadIdx.x;
    float cs = g_cpart[0][i] + g_cpart[1][i] + g_cpart[2][i] + g_cpart[3][i];
    g_dinv0[i] = 1.0f / (cs + 1.0f);
    g_dinv1[i] = 1.0f / (g_rowsum[i] + 1.0f);
}

// ------------------------------ X1 = [xin | h]; Z chunk0 full fp32 ---------
__global__ void k_buildX1(const float* __restrict__ inp, const float* __restrict__ hx) {
    int idx = blockIdx.x * 256 + threadIdx.x;    // Mrows * 32 float4s
    int f4 = idx & 31;
    int row = idx >> 5;
    float4 v = (f4 < 16) ? ld4(&inp[row * Uu + f4 * 4]) : ld4(&hx[row * Uu + (f4 - 16) * 4]);
    st4(&g_Z[(size_t)row * DIN + f4 * 4], v);         // full precision into Z
    st4(&g_X1[row * DU + f4 * 4], to_tf32_4(v));      // rounded gemm operand
}

// ------------------------------ big batched GEMM (tf32, paired cp.async) ---
// PHASE 1: Z cols <- dinv*(A(T)@X1 + X1).  PHASE 2: <- dinv*(A(T)@XRH + XRH)
template <int PHASE>
__global__ __launch_bounds__(256) void k_gemm_tc() {
    constexpr int BN = (PHASE == 1) ? DU : Uu;
    constexpr int BM = 128, BK = 8, STAGES = 4;
    constexpr int ASZ = 1536;
    constexpr int BSTR = BN + 8;
    constexpr int BSZ = BK * BSTR;
    constexpr int wn_ = (BN == 128) ? 4 : 2;
    constexpr int wm_ = 8 / wn_;
    constexpr int mf_ = (BM / wm_) / 16;
    constexpr int nf_ = (BN / wn_) / 8;
    const int b = blockIdx.z, trans = blockIdx.y;
    const int m0 = blockIdx.x * BM;
    const int zcol0 = (PHASE == 1) ? (trans ? 256 : 128) : (trans ? 320 : 192);

    const float* A = g_adj + (size_t)b * Nn * Nn;
    const float* X = ((PHASE == 1) ? g_X1 : g_XRH) + (size_t)b * Nn * BN;
    const float* dinv = (trans ? g_dinv1 : g_dinv0);

    __shared__ float As[STAGES * ASZ];
    __shared__ float Bs[STAGES * BSZ];

    const int tid  = threadIdx.x;
    const int w    = tid >> 5;
    const int lane = tid & 31;
    const int g4   = lane >> 2;
    const int t4   = lane & 3;
    const int warp_m = (w % wm_) * (BM / wm_);
    const int warp_n = (w / wm_) * (BN / wn_);

    float acc[mf_][nf_][4];
    #pragma unroll
    for (int i = 0; i < mf_; i++)
        #pragma unroll
        for (int j = 0; j < nf_; j++)
            #pragma unroll
            for (int r = 0; r < 4; r++) acc[i][j][r] = 0.0f;

    auto issue1 = [&](int st, int k0) {
        float* as = As + st * ASZ;
        float* bs = Bs + st * BSZ;
        if (!trans) {
            int r = tid >> 1, c = (tid & 1) * 4;
            cpasync16(&as[r * 12 + c], &A[(size_t)(m0 + r) * Nn + k0 + c]);
        } else {
            int k = tid >> 5, c = (tid & 31) * 4;
            cpasync16(&as[k * 136 + c], &A[(size_t)(k0 + k) * Nn + m0 + c]);
        }
        if (BN == 128) {
            int k = tid >> 5, c = (tid & 31) * 4;
            cpasync16(&bs[k * BSTR + c], &X[(k0 + k) * BN + c]);
        } else if (tid < 128) {
            int k = tid >> 4, c = (tid & 15) * 4;
            cpasync16(&bs[k * BSTR + c], &X[(k0 + k) * BN + c]);
        }
    };
    auto issuePair = [&](int pair, int k0) {
        issue1((pair & 1) * 2,     k0);
        issue1((pair & 1) * 2 + 1, k0 + BK);
        cp_commit();
    };

    constexpr int NP = Nn / (2 * BK);   // 64
    issuePair(0, 0);
    issuePair(1, 2 * BK);

    for (int t = 0; t < NP; t++) {
        cp_wait<1>();
        __syncthreads();
        #pragma unroll
        for (int sub = 0; sub < 2; sub++) {
            const int st = (t & 1) * 2 + sub;
            const float* as = As + st * ASZ;
            const float* bs = Bs + st * BSZ;
            float a[mf_][4];
            if (!trans) {
                #pragma unroll
                for (int mf = 0; mf < mf_; mf++) {
                    int row = warp_m + mf * 16 + g4;
                    a[mf][0] = as[ row      * 12 + t4    ];
                    a[mf][1] = as[(row + 8) * 12 + t4    ];
                    a[mf][2] = as[ row      * 12 + t4 + 4];
                    a[mf][3] = as[(row + 8) * 12 + t4 + 4];
                }
            } else {
                #pragma unroll
                for (int mf = 0; mf < mf_; mf++) {
                    int row = warp_m + mf * 16 + g4;
                    a[mf][0] = as[ t4      * 136 + row    ];
                    a[mf][1] = as[ t4      * 136 + row + 8];
                    a[mf][2] = as[(t4 + 4) * 136 + row    ];
                    a[mf][3] = as[(t4 + 4) * 136 + row + 8];
                }
            }
            #pragma unroll
            for (int nf = 0; nf < nf_; nf++) {
                int col = warp_n + nf * 8 + g4;
                float b0 = bs[ t4      * BSTR + col];
                float b1 = bs[(t4 + 4) * BSTR + col];
                #pragma unroll
                for (int mf = 0; mf < mf_; mf++)
                    mma_tf32(acc[mf][nf], a[mf][0], a[mf][1], a[mf][2], a[mf][3], b0, b1);
            }
        }
        if (t + 2 < NP) issuePair(t + 2, (t + 2) * 2 * BK);
        else cp_commit();
    }

    #pragma unroll
    for (int mf = 0; mf < mf_; mf++) {
        #pragma unroll
        for (int half = 0; half < 2; half++) {
            int rloc = warp_m + mf * 16 + g4 + half * 8;
            int rglob = b * Nn + m0 + rloc;
            float d = dinv[rglob];
            #pragma unroll
            for (int nf = 0; nf < nf_; nf++) {
                int cc = warp_n + nf * 8 + 2 * t4;
                float2 x = *reinterpret_cast<const float2*>(&X[(size_t)(m0 + rloc) * BN + cc]);
                float v0 = d * (acc[mf][nf][half * 2 + 0] + x.x);
                float v1 = d * (acc[mf][nf][half * 2 + 1] + x.y);
                *reinterpret_cast<float2*>(&g_Z[(size_t)rglob * DIN + zcol0 + cc]) =
                    make_float2(v0, v1);
            }
        }
    }
}

// ------------------------------ weight GEMMs (3xTF32, in-register split) ---
// smem: fp32 Z stage + fp32 W stage; hi/lo split happens in registers.
// WHICH=1: sigmoid(Z @ W1^T + b1s) -> XRH=r*h (also Z[:,64:128]), Ug.
// WHICH=2: tanh(Z @ Wc^T + bcs) -> out = u*h + (1-u)*c.
template <int WHICH>
__global__ __launch_bounds__(256) void k_wgemm(const float* __restrict__ hx,
                                               float* __restrict__ out) {
    constexpr int BN = (WHICH == 1) ? DU : Uu;
    constexpr int BM = 128, BK = 8, STAGES = 3;
    constexpr int ASZ = BM * 12;
    constexpr int WSZ = BN * 12;
    constexpr int wn_ = (BN == 128) ? 4 : 2;
    constexpr int wm_ = 8 / wn_;
    constexpr int mf_ = (BM / wm_) / 16;
    constexpr int nf_ = (BN / wn_) / 8;

    const int m0 = blockIdx.x * BM;
    const float* Wc = (WHICH == 1) ? g_W1cat : g_Wccat;

    __shared__ float As[STAGES * ASZ];
    __shared__ float Ws[STAGES * WSZ];

    const int tid  = threadIdx.x;
    const int w    = tid >> 5;
    const int lane = tid & 31;
    const int g4   = lane >> 2;
    const int t4   = lane & 3;
    const int warp_m = (w % wm_) * (BM / wm_);
    const int warp_n = (w / wm_) * (BN / wn_);

    float acc[mf_][nf_][4];
    #pragma unroll
    for (int i = 0; i < mf_; i++)
        #pragma unroll
        for (int j = 0; j < nf_; j++)
            #pragma unroll
            for (int r = 0; r < 4; r++) acc[i][j][r] = 0.0f;

    auto issue = [&](int st, int k0) {
        float* as = As + st * ASZ;
        float* ws = Ws + st * WSZ;
        {
            int r = tid >> 1, c = (tid & 1) * 4;
            cpasync16(&as[r * 12 + c], &g_Z[(size_t)(m0 + r) * DIN + k0 + c]);
        }
        if (BN == 128) {
            int n = tid >> 1, c = (tid & 1) * 4;
            cpasync16(&ws[n * 12 + c], &Wc[n * DIN + k0 + c]);
        } else if (tid < 128) {
            int n = tid >> 1, c = (tid & 1) * 4;
            cpasync16(&ws[n * 12 + c], &Wc[n * DIN + k0 + c]);
        }
        cp_commit();
    };

    constexpr int NT = DIN / BK;   // 48
    issue(0, 0); issue(1, BK);

    int st = 0;
    for (int kt = 0; kt < NT; kt++) {
        cp_wait<STAGES - 2>();
        __syncthreads();
        const float* as = As + st * ASZ;
        const float* ws = Ws + st * WSZ;

        float ahi[mf_][4], alo[mf_][4];
        #pragma unroll
        for (int mf = 0; mf < mf_; mf++) {
            int row = warp_m + mf * 16 + g4;
            float z0 = as[ row      * 12 + t4    ];
            float z1 = as[(row + 8) * 12 + t4    ];
            float z2 = as[ row      * 12 + t4 + 4];
            float z3 = as[(row + 8) * 12 + t4 + 4];
            ahi[mf][0] = to_tf32(z0); alo[mf][0] = to_tf32(z0 - ahi[mf][0]);
            ahi[mf][1] = to_tf32(z1); alo[mf][1] = to_tf32(z1 - ahi[mf][1]);
            ahi[mf][2] = to_tf32(z2); alo[mf][2] = to_tf32(z2 - ahi[mf][2]);
            ahi[mf][3] = to_tf32(z3); alo[mf][3] = to_tf32(z3 - ahi[mf][3]);
        }
        #pragma unroll
        for (int nf = 0; nf < nf_; nf++) {
            int col = warp_n + nf * 8 + g4;
            float w0 = ws[col * 12 + t4    ];
            float w1 = ws[col * 12 + t4 + 4];
            float h0 = to_tf32(w0), l0 = to_tf32(w0 - h0);
            float h1 = to_tf32(w1), l1 = to_tf32(w1 - h1);
            #pragma unroll
            for (int mf = 0; mf < mf_; mf++) {
                mma_tf32(acc[mf][nf], alo[mf][0], alo[mf][1], alo[mf][2], alo[mf][3], h0, h1);
                mma_tf32(acc[mf][nf], ahi[mf][0], ahi[mf][1], ahi[mf][2], ahi[mf][3], l0, l1);
                mma_tf32(acc[mf][nf], ahi[mf][0], ahi[mf][1], ahi[mf][2], ahi[mf][3], h0, h1);
            }
        }

        if (kt + STAGES - 1 < NT) issue((kt + STAGES - 1) % STAGES, (kt + STAGES - 1) * BK);
        else cp_commit();
        st = (st + 1 == STAGES) ? 0 : st + 1;
    }

    #pragma unroll
    for (int mf = 0; mf < mf_; mf++) {
        #pragma unroll
        for (int nf = 0; nf < nf_; nf++) {
            #pragma unroll
            for (int half = 0; half < 2; half++) {
                int row = m0 + warp_m + mf * 16 + g4 + half * 8;
                #pragma unroll
                for (int e = 0; e < 2; e++) {
                    int o = warp_n + nf * 8 + 2 * t4 + e;
                    float v = acc[mf][nf][half * 2 + e];
                    if (WHICH == 1) {
                        float val = sigm(v + g_b1s[o]);
                        if (o < Uu) {
                            float rh = val * hx[row * Uu + o];
                            g_XRH[row * Uu + o] = to_tf32(rh);
                            g_Z[(size_t)row * DIN + Uu + o] = rh;
                        } else {
                            g_Ug[row * Uu + o - Uu] = val;
                        }
                    } else {
                        float c = tanhf(v + g_bcs[o]);
                        float u = g_Ug[row * Uu + o];
                        float h = hx[row * Uu + o];
                        out[row * Uu + o] = u * h + (1.0f - u) * c;
                    }
                }
            }
        }
    }
}

// ------------------------------ launch -------------------------------------
extern "C" void kernel_launch(void* const* d_in, const int* in_sizes, int n_in,
                              void* d_out, int out_size) {
    (void)in_sizes; (void)n_in; (void)out_size;
    const float* logits = (const float*)d_in[0];
    const float* u_noise = (const float*)d_in[1];
    const float* inputs = (const float*)d_in[2];
    const float* hx = (const float*)d_in[3];
    const float* W0 = (const float*)d_in[4];
    const float* b0 = (const float*)d_in[5];
    const float* W1 = (const float*)d_in[6];
    const float* b1 = (const float*)d_in[7];
    const float* Wc0 = (const float*)d_in[8];
    const float* bc0 = (const float*)d_in[9];
    const float* Wc1 = (const float*)d_in[10];
    const float* bc1 = (const float*)d_in[11];
    float* out = (float*)d_out;

    k_prep<<<64, 256>>>(W0, b0, W1, b1, Wc0, bc0, Wc1, bc1);
    k_adj<<<dim3(Nn, Bb), 256>>>((const float4*)logits, (const float4*)u_noise);
    k_colsum_part<<<dim3(Nn / 256, Bb, 4), 256>>>();
    k_dinv<<<Mrows / 256, 256>>>();
    k_buildX1<<<(Mrows * 32) / 256, 256>>>(inputs, hx);
    k_gemm_tc<1><<<dim3(Nn / 128, 2, Bb), 256>>>();
    k_wgemm<1><<<Mrows / 128, 256>>>(hx, out);
    k_gemm_tc<2><<<dim3(Nn / 128, 2, Bb), 256>>>();
    k_wgemm<2><<<Mrows / 128, 256>>>(hx, out);
}

// round 9
// speedup vs baseline: 1.0825x; 1.0825x over previous
#include <cuda_runtime.h>
#include <math.h>

// ---------------------------------------------------------------------------
// GRELEN: gumbel-softmax adjacency + 2x diffusion-GCN GRU cell
// B=16, N=1024, U=64, K=2  (reference stacks [x, Ax, Ax] due to its loop quirk)
// R9: precise inner log in k_adj (the real rel_err source), single-pass tf32
//     weight GEMMs (rna in-register), B operands streamed from fp32 Z.
// ---------------------------------------------------------------------------

namespace {
constexpr int Bb   = 16;
constexpr int Nn   = 1024;
constexpr int Uu   = 64;
constexpr int DU   = 128;   // 2U
constexpr int DIN  = 384;   // 2U*(K+1)
constexpr int Mrows = Bb * Nn;       // 16384
constexpr float EPSc = 1e-10f;
}

// ------------------------------ scratch ------------------------------------
__device__ float g_adj[(size_t)Bb * Nn * Nn];   // 64 MB (tf32-rounded)
__device__ float g_rowsum[Mrows];
__device__ float g_cpart[4][Mrows];
__device__ float g_dinv0[Mrows];
__device__ float g_dinv1[Mrows];
__device__ float g_Ug [Mrows * Uu];
__device__ float g_Z  [(size_t)Mrows * DIN];    // FULL fp32 shared Z1->Z2 staging
__device__ float g_W1cat[DU * DIN];             // full fp32 folded weights
__device__ float g_Wccat[Uu * DIN];
__device__ float g_b1s[DU];
__device__ float g_bcs[Uu];

__device__ __forceinline__ float4 ld4(const float* p) { return *reinterpret_cast<const float4*>(p); }
__device__ __forceinline__ void   st4(float* p, float4 v) { *reinterpret_cast<float4*>(p) = v; }
__device__ __forceinline__ float sigm(float x) { return 1.0f / (1.0f + expf(-x)); }

__device__ __forceinline__ float to_tf32(float x) {
    unsigned u;
    asm("cvt.rna.tf32.f32 %0, %1;" : "=r"(u) : "f"(x));
    return __uint_as_float(u);
}

__device__ __forceinline__ void cpasync16(float* dst_smem, const float* src) {
    unsigned d = (unsigned)__cvta_generic_to_shared(dst_smem);
    asm volatile("cp.async.cg.shared.global [%0], [%1], 16;\n" :: "r"(d), "l"(src));
}
__device__ __forceinline__ void cp_commit() {
    asm volatile("cp.async.commit_group;\n" ::: "memory");
}
template <int N>
__device__ __forceinline__ void cp_wait() {
    asm volatile("cp.async.wait_group %0;\n" :: "n"(N) : "memory");
}

__device__ __forceinline__ void mma_tf32(float (&d)[4], const float a0, const float a1,
                                         const float a2, const float a3,
                                         const float b0, const float b1) {
    asm volatile(
        "mma.sync.aligned.m16n8k8.row.col.f32.tf32.tf32.f32 "
        "{%0,%1,%2,%3}, {%4,%5,%6,%7}, {%8,%9}, {%0,%1,%2,%3};\n"
        : "+f"(d[0]), "+f"(d[1]), "+f"(d[2]), "+f"(d[3])
        : "r"(__float_as_uint(a0)), "r"(__float_as_uint(a1)),
          "r"(__float_as_uint(a2)), "r"(__float_as_uint(a3)),
          "r"(__float_as_uint(b0)), "r"(__float_as_uint(b1)));
}

// ------------------------------ weight folding (full fp32) -----------------
__global__ void k_prep(const float* __restrict__ W0, const float* __restrict__ b0,
                       const float* __restrict__ W1, const float* __restrict__ b1,
                       const float* __restrict__ Wc0, const float* __restrict__ bc0,
                       const float* __restrict__ Wc1, const float* __restrict__ bc1) {
    int t = blockIdx.x * blockDim.x + threadIdx.x;
    int stride = gridDim.x * blockDim.x;
    for (int idx = t; idx < DU * DIN; idx += stride) {
        int o = idx / DIN, k = idx % DIN;
        float v;
        if (k < DU)            v = W0[o*DIN + 3*k]     + W1[o*DIN + 3*k];
        else if (k < 2*DU)   { int f = k - DU;   v = W0[o*DIN + 3*f+1] + W0[o*DIN + 3*f+2]; }
        else                 { int f = k - 2*DU; v = W1[o*DIN + 3*f+1] + W1[o*DIN + 3*f+2]; }
        g_W1cat[idx] = v;
    }
    for (int idx = t; idx < Uu * DIN; idx += stride) {
        int o = idx / DIN, k = idx % DIN;
        float v;
        if (k < DU)            v = Wc0[o*DIN + 3*k]     + Wc1[o*DIN + 3*k];
        else if (k < 2*DU)   { int f = k - DU;   v = Wc0[o*DIN + 3*f+1] + Wc0[o*DIN + 3*f+2]; }
        else                 { int f = k - 2*DU; v = Wc1[o*DIN + 3*f+1] + Wc1[o*DIN + 3*f+2]; }
        g_Wccat[idx] = v;
    }
    if (t < DU) g_b1s[t] = b0[t] + b1[t];
    if (t < Uu) g_bcs[t] = bc0[t] + bc1[t];
}

// ------------------------------ adjacency + row sums -----------------------
// p = 1 / (1 + e^{2(l1-l0)} (t0/t1)^2),  t_i = eps - log(u_i+eps)
// Inner log MUST be precise (libm logf): __logf's absolute error blows up the
// relative error of t as u->1 (t->0), which dominated rel_err in R4-R8.
__global__ void k_adj(const float4* __restrict__ logits4, const float4* __restrict__ un4) {
    int b = blockIdx.y, i = blockIdx.x, t = threadIdx.x;
    size_t base4 = (size_t)(b * Nn + i) * (Nn / 2);
    float2* adj2 = reinterpret_cast<float2*>(g_adj + (size_t)(b * Nn + i) * Nn);
    float s = 0.0f;
    #pragma unroll
    for (int j = t; j < Nn / 2; j += 256) {
        float4 l = logits4[base4 + j];
        float4 u = un4[base4 + j];
        float t0a = EPSc - logf(u.x + EPSc), t1a = EPSc - logf(u.y + EPSc);
        float t0b = EPSc - logf(u.z + EPSc), t1b = EPSc - logf(u.w + EPSc);
        float ra = __fdividef(t0a, t1a);
        float rb = __fdividef(t0b, t1b);
        float wa = __expf(2.0f * (l.y - l.x)) * ra * ra;
        float wb = __expf(2.0f * (l.w - l.z)) * rb * rb;
        float pa = to_tf32(__fdividef(1.0f, 1.0f + wa));
        float pb = to_tf32(__fdividef(1.0f, 1.0f + wb));
        adj2[j] = make_float2(pa, pb);
        s += pa + pb;
    }
    #pragma unroll
    for (int o = 16; o; o >>= 1) s += __shfl_down_sync(0xffffffffu, s, o);
    __shared__ float red[8];
    if ((t & 31) == 0) red[t >> 5] = s;
    __syncthreads();
    if (t == 0) {
        float tot = 0.0f;
        #pragma unroll
        for (int w = 0; w < 8; w++) tot += red[w];
        g_rowsum[b * Nn + i] = tot;
    }
}

// ------------------------------ column sums (4 partials) -------------------
__global__ void k_colsum_part() {
    int b = blockIdx.y, q = blockIdx.z;
    int j = blockIdx.x * 256 + threadIdx.x;
    size_t base = (size_t)b * Nn * Nn + (size_t)q * (Nn / 4) * Nn + j;
    float s = 0.0f;
    #pragma unroll 8
    for (int i = 0; i < Nn / 4; i++) s += g_adj[base + (size_t)i * Nn];
    g_cpart[q][b * Nn + j] = s;
}

// ------------------------------ Z chunk0 = [xin | h] (fp32) + dinv ---------
__global__ void k_buildZ0(const float* __restrict__ inp, const float* __restrict__ hx) {
    int idx = blockIdx.x * 256 + threadIdx.x;    // Mrows * 32 float4s
    int f4 = idx & 31;
    int row = idx >> 5;
    float4 v = (f4 < 16) ? ld4(&inp[row * Uu + f4 * 4]) : ld4(&hx[row * Uu + (f4 - 16) * 4]);
    st4(&g_Z[(size_t)row * DIN + f4 * 4], v);
    if (idx < Mrows) {
        float cs = g_cpart[0][idx] + g_cpart[1][idx] + g_cpart[2][idx] + g_cpart[3][idx];
        g_dinv0[idx] = 1.0f / (cs + 1.0f);
        g_dinv1[idx] = 1.0f / (g_rowsum[idx] + 1.0f);
    }
}

// ------------------------------ big batched GEMM (tf32, paired cp.async) ---
// B operand streams from fp32 Z chunk0 (cols xoff..xoff+BN); rna in-register.
// PHASE 1: Z cols <- dinv*(A(T)@[x|h] + [x|h]).  PHASE 2: <- dinv*(A(T)@rh + rh)
template <int PHASE>
__global__ __launch_bounds__(256) void k_gemm_tc() {
    constexpr int BN = (PHASE == 1) ? DU : Uu;
    constexpr int XOFF = (PHASE == 1) ? 0 : 64;     // column offset in Z chunk0
    constexpr int BM = 128, BK = 8, STAGES = 4;
    constexpr int ASZ = 1536;
    constexpr int BSTR = BN + 8;
    constexpr int BSZ = BK * BSTR;
    constexpr int wn_ = (BN == 128) ? 4 : 2;
    constexpr int wm_ = 8 / wn_;
    constexpr int mf_ = (BM / wm_) / 16;
    constexpr int nf_ = (BN / wn_) / 8;
    const int b = blockIdx.z, trans = blockIdx.y;
    const int m0 = blockIdx.x * BM;
    const int zcol0 = (PHASE == 1) ? (trans ? 256 : 128) : (trans ? 320 : 192);

    const float* A = g_adj + (size_t)b * Nn * Nn;
    const float* Zb = g_Z + (size_t)b * Nn * DIN + XOFF;   // B operand rows, stride DIN
    const float* dinv = (trans ? g_dinv1 : g_dinv0);

    __shared__ float As[STAGES * ASZ];
    __shared__ float Bs[STAGES * BSZ];

    const int tid  = threadIdx.x;
    const int w    = tid >> 5;
    const int lane = tid & 31;
    const int g4   = lane >> 2;
    const int t4   = lane & 3;
    const int warp_m = (w % wm_) * (BM / wm_);
    const int warp_n = (w / wm_) * (BN / wn_);

    float acc[mf_][nf_][4];
    #pragma unroll
    for (int i = 0; i < mf_; i++)
        #pragma unroll
        for (int j = 0; j < nf_; j++)
            #pragma unroll
            for (int r = 0; r < 4; r++) acc[i][j][r] = 0.0f;

    auto issue1 = [&](int st, int k0) {
        float* as = As + st * ASZ;
        float* bs = Bs + st * BSZ;
        if (!trans) {
            int r = tid >> 1, c = (tid & 1) * 4;
            cpasync16(&as[r * 12 + c], &A[(size_t)(m0 + r) * Nn + k0 + c]);
        } else {
            int k = tid >> 5, c = (tid & 31) * 4;
            cpasync16(&as[k * 136 + c], &A[(size_t)(k0 + k) * Nn + m0 + c]);
        }
        if (BN == 128) {
            int k = tid >> 5, c = (tid & 31) * 4;
            cpasync16(&bs[k * BSTR + c], &Zb[(size_t)(k0 + k) * DIN + c]);
        } else if (tid < 128) {
            int k = tid >> 4, c = (tid & 15) * 4;
            cpasync16(&bs[k * BSTR + c], &Zb[(size_t)(k0 + k) * DIN + c]);
        }
    };
    auto issuePair = [&](int pair, int k0) {
        issue1((pair & 1) * 2,     k0);
        issue1((pair & 1) * 2 + 1, k0 + BK);
        cp_commit();
    };

    constexpr int NP = Nn / (2 * BK);   // 64
    issuePair(0, 0);
    issuePair(1, 2 * BK);

    for (int t = 0; t < NP; t++) {
        cp_wait<1>();
        __syncthreads();
        #pragma unroll
        for (int sub = 0; sub < 2; sub++) {
            const int st = (t & 1) * 2 + sub;
            const float* as = As + st * ASZ;
            const float* bs = Bs + st * BSZ;
            float a[mf_][4];
            if (!trans) {
                #pragma unroll
                for (int mf = 0; mf < mf_; mf++) {
                    int row = warp_m + mf * 16 + g4;
                    a[mf][0] = as[ row      * 12 + t4    ];
                    a[mf][1] = as[(row + 8) * 12 + t4    ];
                    a[mf][2] = as[ row      * 12 + t4 + 4];
                    a[mf][3] = as[(row + 8) * 12 + t4 + 4];
                }
            } else {
                #pragma unroll
                for (int mf = 0; mf < mf_; mf++) {
                    int row = warp_m + mf * 16 + g4;
                    a[mf][0] = as[ t4      * 136 + row    ];
                    a[mf][1] = as[ t4      * 136 + row + 8];
                    a[mf][2] = as[(t4 + 4) * 136 + row    ];
                    a[mf][3] = as[(t4 + 4) * 136 + row + 8];
                }
            }
            #pragma unroll
            for (int nf = 0; nf < nf_; nf++) {
                int col = warp_n + nf * 8 + g4;
                float b0 = to_tf32(bs[ t4      * BSTR + col]);
                float b1 = to_tf32(bs[(t4 + 4) * BSTR + col]);
                #pragma unroll
                for (int mf = 0; mf < mf_; mf++)
                    mma_tf32(acc[mf][nf], a[mf][0], a[mf][1], a[mf][2], a[mf][3], b0, b1);
            }
        }
        if (t + 2 < NP) issuePair(t + 2, (t + 2) * 2 * BK);
        else cp_commit();
    }

    // epilogue: Z[row, zcol0+col] = dinv[row] * (acc + Zchunk0[row, XOFF+col])
    #pragma unroll
    for (int mf = 0; mf < mf_; mf++) {
        #pragma unroll
        for (int half = 0; half < 2; half++) {
            int rloc = warp_m + mf * 16 + g4 + half * 8;
            int rglob = b * Nn + m0 + rloc;
            float d = dinv[rglob];
            #pragma unroll
            for (int nf = 0; nf < nf_; nf++) {
                int cc = warp_n + nf * 8 + 2 * t4;
                float2 x = *reinterpret_cast<const float2*>(
                    &g_Z[(size_t)rglob * DIN + XOFF + cc]);
                float v0 = d * (acc[mf][nf][half * 2 + 0] + x.x);
                float v1 = d * (acc[mf][nf][half * 2 + 1] + x.y);
                *reinterpret_cast<float2*>(&g_Z[(size_t)rglob * DIN + zcol0 + cc]) =
                    make_float2(v0, v1);
            }
        }
    }
}

// ------------------------------ weight GEMMs (tf32, rna in-register) -------
// WHICH=1: sigmoid(Z @ W1^T + b1s) -> Z[:,64:128]=r*h (fp32), Ug.
// WHICH=2: tanh(Z @ Wc^T + bcs) -> out = u*h + (1-u)*c.
template <int WHICH>
__global__ __launch_bounds__(256) void k_wgemm(const float* __restrict__ hx,
                                               float* __restrict__ out) {
    constexpr int BN = (WHICH == 1) ? DU : Uu;
    constexpr int BM = 128, BK = 8, STAGES = 3;
    constexpr int ASZ = BM * 12;
    constexpr int WSZ = BN * 12;
    constexpr int wn_ = (BN == 128) ? 4 : 2;
    constexpr int wm_ = 8 / wn_;
    constexpr int mf_ = (BM / wm_) / 16;
    constexpr int nf_ = (BN / wn_) / 8;

    const int m0 = blockIdx.x * BM;
    const float* Wc = (WHICH == 1) ? g_W1cat : g_Wccat;

    __shared__ float As[STAGES * ASZ];
    __shared__ float Ws[STAGES * WSZ];

    const int tid  = threadIdx.x;
    const int w    = tid >> 5;
    const int lane = tid & 31;
    const int g4   = lane >> 2;
    const int t4   = lane & 3;
    const int warp_m = (w % wm_) * (BM / wm_);
    const int warp_n = (w / wm_) * (BN / wn_);

    float acc[mf_][nf_][4];
    #pragma unroll
    for (int i = 0; i < mf_; i++)
        #pragma unroll
        for (int j = 0; j < nf_; j++)
            #pragma unroll
            for (int r = 0; r < 4; r++) acc[i][j][r] = 0.0f;

    auto issue = [&](int st, int k0) {
        float* as = As + st * ASZ;
        float* ws = Ws + st * WSZ;
        {
            int r = tid >> 1, c = (tid & 1) * 4;
            cpasync16(&as[r * 12 + c], &g_Z[(size_t)(m0 + r) * DIN + k0 + c]);
        }
        if (BN == 128) {
            int n = tid >> 1, c = (tid & 1) * 4;
            cpasync16(&ws[n * 12 + c], &Wc[n * DIN + k0 + c]);
        } else if (tid < 128) {
            int n = tid >> 1, c = (tid & 1) * 4;
            cpasync16(&ws[n * 12 + c], &Wc[n * DIN + k0 + c]);
        }
        cp_commit();
    };

    constexpr int NT = DIN / BK;   // 48
    issue(0, 0); issue(1, BK);

    int st = 0;
    for (int kt = 0; kt < NT; kt++) {
        cp_wait<STAGES - 2>();
        __syncthreads();
        const float* as = As + st * ASZ;
        const float* ws = Ws + st * WSZ;

        float a[mf_][4];
        #pragma unroll
        for (int mf = 0; mf < mf_; mf++) {
            int row = warp_m + mf * 16 + g4;
            a[mf][0] = to_tf32(as[ row      * 12 + t4    ]);
            a[mf][1] = to_tf32(as[(row + 8) * 12 + t4    ]);
            a[mf][2] = to_tf32(as[ row      * 12 + t4 + 4]);
            a[mf][3] = to_tf32(as[(row + 8) * 12 + t4 + 4]);
        }
        #pragma unroll
        for (int nf = 0; nf < nf_; nf++) {
            int col = warp_n + nf * 8 + g4;
            float b0 = to_tf32(ws[col * 12 + t4    ]);
            float b1 = to_tf32(ws[col * 12 + t4 + 4]);
            #pragma unroll
            for (int mf = 0; mf < mf_; mf++)
                mma_tf32(acc[mf][nf], a[mf][0], a[mf][1], a[mf][2], a[mf][3], b0, b1);
        }

        if (kt + STAGES - 1 < NT) issue((kt + STAGES - 1) % STAGES, (kt + STAGES - 1) * BK);
        else cp_commit();
        st = (st + 1 == STAGES) ? 0 : st + 1;
    }

    #pragma unroll
    for (int mf = 0; mf < mf_; mf++) {
        #pragma unroll
        for (int nf = 0; nf < nf_; nf++) {
            #pragma unroll
            for (int half = 0; half < 2; half++) {
                int row = m0 + warp_m + mf * 16 + g4 + half * 8;
                #pragma unroll
                for (int e = 0; e < 2; e++) {
                    int o = warp_n + nf * 8 + 2 * t4 + e;
                    float v = acc[mf][nf][half * 2 + e];
                    if (WHICH == 1) {
                        float val = sigm(v + g_b1s[o]);
                        if (o < Uu) {
                            g_Z[(size_t)row * DIN + Uu + o] = val * hx[row * Uu + o];
                        } else {
                            g_Ug[row * Uu + o - Uu] = val;
                        }
                    } else {
                        float c = tanhf(v + g_bcs[o]);
                        float u = g_Ug[row * Uu + o];
                        float h = hx[row * Uu + o];
                        out[row * Uu + o] = u * h + (1.0f - u) * c;
                    }
                }
            }
        }
    }
}

// ------------------------------ launch -------------------------------------
extern "C" void kernel_launch(void* const* d_in, const int* in_sizes, int n_in,
                              void* d_out, int out_size) {
    (void)in_sizes; (void)n_in; (void)out_size;
    const float* logits = (const float*)d_in[0];
    const float* u_noise = (const float*)d_in[1];
    const float* inputs = (const float*)d_in[2];
    const float* hx = (const float*)d_in[3];
    const float* W0 = (const float*)d_in[4];
    const float* b0 = (const float*)d_in[5];
    const float* W1 = (const float*)d_in[6];
    const float* b1 = (const float*)d_in[7];
    const float* Wc0 = (const float*)d_in[8];
    const float* bc0 = (const float*)d_in[9];
    const float* Wc1 = (const float*)d_in[10];
    const float* bc1 = (const float*)d_in[11];
    float* out = (float*)d_out;

    k_prep<<<64, 256>>>(W0, b0, W1, b1, Wc0, bc0, Wc1, bc1);
    k_adj<<<dim3(Nn, Bb), 256>>>((const float4*)logits, (const float4*)u_noise);
    k_colsum_part<<<dim3(Nn / 256, Bb, 4), 256>>>();
    k_buildZ0<<<(Mrows * 32) / 256, 256>>>(inputs, hx);
    k_gemm_tc<1><<<dim3(Nn / 128, 2, Bb), 256>>>();
    k_wgemm<1><<<Mrows / 128, 256>>>(hx, out);
    k_gemm_tc<2><<<dim3(Nn / 128, 2, Bb), 256>>>();
    k_wgemm<2><<<Mrows / 128, 256>>>(hx, out);
}

// round 10
// speedup vs baseline: 1.6615x; 1.5348x over previous
#include <cuda_runtime.h>
#include <cuda_fp16.h>
#include <math.h>

// ---------------------------------------------------------------------------
// GRELEN: gumbel-softmax adjacency + 2x diffusion-GCN GRU cell
// B=16, N=1024, U=64, K=2  (reference stacks [x, Ax, Ax] due to its loop quirk)
// R10: fp16 operands everywhere (same 10-bit mantissa as tf32), m16n8k16 mma,
//      ldmatrix fragments, halved adj/Z/W traffic. Precise inner log kept.
// ---------------------------------------------------------------------------

namespace {
constexpr int Bb   = 16;
constexpr int Nn   = 1024;
constexpr int Uu   = 64;
constexpr int DU   = 128;   // 2U
constexpr int DIN  = 384;   // 2U*(K+1)
constexpr int Mrows = Bb * Nn;       // 16384
constexpr float EPSc = 1e-10f;
}

// ------------------------------ scratch ------------------------------------
__device__ __half g_adjh[(size_t)Bb * Nn * Nn];   // 32 MB fp16 adjacency
__device__ float  g_rowsum[Mrows];
__device__ float  g_cpart[4][Mrows];
__device__ float  g_dinv0[Mrows];
__device__ float  g_dinv1[Mrows];
__device__ float  g_Ug [Mrows * Uu];
__device__ __half g_Zh [(size_t)Mrows * DIN];     // 12.5 MB fp16 Z staging
__device__ __half g_W1h[DU * DIN];                // fp16 folded weights
__device__ __half g_Wch[Uu * DIN];
__device__ float  g_b1s[DU];
__device__ float  g_bcs[Uu];

__device__ __forceinline__ float4 ld4(const float* p) { return *reinterpret_cast<const float4*>(p); }
__device__ __forceinline__ float sigm(float x) { return 1.0f / (1.0f + expf(-x)); }

__device__ __forceinline__ void cpasync16(void* dst_smem, const void* src) {
    unsigned d = (unsigned)__cvta_generic_to_shared(dst_smem);
    asm volatile("cp.async.cg.shared.global [%0], [%1], 16;\n" :: "r"(d), "l"(src));
}
__device__ __forceinline__ void cp_commit() {
    asm volatile("cp.async.commit_group;\n" ::: "memory");
}
template <int N>
__device__ __forceinline__ void cp_wait() {
    asm volatile("cp.async.wait_group %0;\n" :: "n"(N) : "memory");
}

__device__ __forceinline__ void ldsm4(unsigned &r0, unsigned &r1, unsigned &r2, unsigned &r3,
                                      unsigned addr) {
    asm volatile("ldmatrix.sync.aligned.m8n8.x4.shared.b16 {%0,%1,%2,%3}, [%4];\n"
                 : "=r"(r0), "=r"(r1), "=r"(r2), "=r"(r3) : "r"(addr));
}
__device__ __forceinline__ void ldsm4t(unsigned &r0, unsigned &r1, unsigned &r2, unsigned &r3,
                                       unsigned addr) {
    asm volatile("ldmatrix.sync.aligned.m8n8.x4.trans.shared.b16 {%0,%1,%2,%3}, [%4];\n"
                 : "=r"(r0), "=r"(r1), "=r"(r2), "=r"(r3) : "r"(addr));
}

__device__ __forceinline__ void mma_f16(float (&d)[4], unsigned a0, unsigned a1,
                                        unsigned a2, unsigned a3,
                                        unsigned b0, unsigned b1) {
    asm volatile(
        "mma.sync.aligned.m16n8k16.row.col.f32.f16.f16.f32 "
        "{%0,%1,%2,%3}, {%4,%5,%6,%7}, {%8,%9}, {%0,%1,%2,%3};\n"
        : "+f"(d[0]), "+f"(d[1]), "+f"(d[2]), "+f"(d[3])
        : "r"(a0), "r"(a1), "r"(a2), "r"(a3), "r"(b0), "r"(b1));
}

// ------------------------------ weight folding -> fp16 ---------------------
__global__ void k_prep(const float* __restrict__ W0, const float* __restrict__ b0,
                       const float* __restrict__ W1, const float* __restrict__ b1,
                       const float* __restrict__ Wc0, const float* __restrict__ bc0,
                       const float* __restrict__ Wc1, const float* __restrict__ bc1) {
    int t = blockIdx.x * blockDim.x + threadIdx.x;
    int stride = gridDim.x * blockDim.x;
    for (int idx = t; idx < DU * DIN; idx += stride) {
        int o = idx / DIN, k = idx % DIN;
        float v;
        if (k < DU)            v = W0[o*DIN + 3*k]     + W1[o*DIN + 3*k];
        else if (k < 2*DU)   { int f = k - DU;   v = W0[o*DIN + 3*f+1] + W0[o*DIN + 3*f+2]; }
        else                 { int f = k - 2*DU; v = W1[o*DIN + 3*f+1] + W1[o*DIN + 3*f+2]; }
        g_W1h[idx] = __float2half_rn(v);
    }
    for (int idx = t; idx < Uu * DIN; idx += stride) {
        int o = idx / DIN, k = idx % DIN;
        float v;
        if (k < DU)            v = Wc0[o*DIN + 3*k]     + Wc1[o*DIN + 3*k];
        else if (k < 2*DU)   { int f = k - DU;   v = Wc0[o*DIN + 3*f+1] + Wc0[o*DIN + 3*f+2]; }
        else                 { int f = k - 2*DU; v = Wc1[o*DIN + 3*f+1] + Wc1[o*DIN + 3*f+2]; }
        g_Wch[idx] = __float2half_rn(v);
    }
    if (t < DU) g_b1s[t] = b0[t] + b1[t];
    if (t < Uu) g_bcs[t] = bc0[t] + bc1[t];
}

// ------------------------------ adjacency + row sums -----------------------
// p = 1 / (1 + e^{2(l1-l0)} (t0/t1)^2), t_i = eps - log(u_i+eps). Inner log
// must be precise (libm): __logf abs-error blows up rel(t) as u->1.
__global__ void k_adj(const float4* __restrict__ logits4, const float4* __restrict__ un4) {
    int b = blockIdx.y, i = blockIdx.x, t = threadIdx.x;
    size_t base4 = (size_t)(b * Nn + i) * (Nn / 2);
    __half2* adj2 = reinterpret_cast<__half2*>(g_adjh + (size_t)(b * Nn + i) * Nn);
    float s = 0.0f;
    for (int j = t; j < Nn / 2; j += 256) {
        float4 l = logits4[base4 + j];
        float4 u = un4[base4 + j];
        float t0a = EPSc - logf(u.x + EPSc), t1a = EPSc - logf(u.y + EPSc);
        float t0b = EPSc - logf(u.z + EPSc), t1b = EPSc - logf(u.w + EPSc);
        float ra = __fdividef(t0a, t1a);
        float rb = __fdividef(t0b, t1b);
        float wa = __expf(2.0f * (l.y - l.x)) * ra * ra;
        float wb = __expf(2.0f * (l.w - l.z)) * rb * rb;
        float pa = __fdividef(1.0f, 1.0f + wa);
        float pb = __fdividef(1.0f, 1.0f + wb);
        __half2 h2 = __floats2half2_rn(pa, pb);
        adj2[j] = h2;
        s += __low2float(h2) + __high2float(h2);   // sum the ROUNDED values
    }
    #pragma unroll
    for (int o = 16; o; o >>= 1) s += __shfl_down_sync(0xffffffffu, s, o);
    __shared__ float red[8];
    if ((t & 31) == 0) red[t >> 5] = s;
    __syncthreads();
    if (t == 0) {
        float tot = 0.0f;
        #pragma unroll
        for (int w = 0; w < 8; w++) tot += red[w];
        g_rowsum[b * Nn + i] = tot;
    }
}

// ------------------------------ column sums (4 partials) -------------------
__global__ void k_colsum_part() {
    int b = blockIdx.y, q = blockIdx.z;
    int j = blockIdx.x * 256 + threadIdx.x;
    const __half* base = g_adjh + (size_t)b * Nn * Nn + (size_t)q * (Nn / 4) * Nn + j;
    float s = 0.0f;
    #pragma unroll 8
    for (int i = 0; i < Nn / 4; i++) s += __half2float(base[(size_t)i * Nn]);
    g_cpart[q][b * Nn + j] = s;
}

// ------------------------------ Z chunk0 = [xin | h] fp16 + dinv -----------
__global__ void k_buildZ0(const float* __restrict__ inp, const float* __restrict__ hx) {
    int idx = blockIdx.x * 256 + threadIdx.x;    // Mrows * 16 chunks of 8 halfs
    int f8 = (idx & 15) * 8;
    int row = idx >> 4;
    const float* src = (f8 < Uu) ? &inp[row * Uu + f8] : &hx[row * Uu + f8 - Uu];
    float4 v0 = ld4(src), v1 = ld4(src + 4);
    __half2 h[4] = { __floats2half2_rn(v0.x, v0.y), __floats2half2_rn(v0.z, v0.w),
                     __floats2half2_rn(v1.x, v1.y), __floats2half2_rn(v1.z, v1.w) };
    *reinterpret_cast<float4*>(&g_Zh[(size_t)row * DIN + f8]) = *reinterpret_cast<float4*>(h);
    if (idx < Mrows) {
        float cs = g_cpart[0][idx] + g_cpart[1][idx] + g_cpart[2][idx] + g_cpart[3][idx];
        g_dinv0[idx] = 1.0f / (cs + 1.0f);
        g_dinv1[idx] = 1.0f / (g_rowsum[idx] + 1.0f);
    }
}

// ------------------------------ big batched GEMM (fp16 mma, cp.async) ------
// PHASE 1: Z cols <- dinv*(A(T)@[x|h] + [x|h]) (BN=128)
// PHASE 2: Z cols <- dinv*(A(T)@rh + rh)       (BN=64)
// A smem: non-trans [m][24] halfs, trans [k][136]. B smem: [k][BN+8].
template <int PHASE>
__global__ __launch_bounds__(256) void k_gemm_tc() {
    constexpr int BN = (PHASE == 1) ? DU : Uu;
    constexpr int XOFF = (PHASE == 1) ? 0 : 64;
    constexpr int BM = 128, BK = 16, STAGES = 4;
    constexpr int ASZ = 3072;                      // halfs: max(128*24, 16*136)
    constexpr int BSTR = BN + 8;                   // 136 or 72
    constexpr int BSZ = BK * BSTR;
    constexpr int wn_ = (BN == 128) ? 4 : 2;
    constexpr int wm_ = 8 / wn_;
    constexpr int mf_ = (BM / wm_) / 16;           // 4 or 2
    constexpr int nf_ = (BN / wn_) / 8;            // 4
    const int b = blockIdx.z, trans = blockIdx.y;
    const int m0 = blockIdx.x * BM;
    const int zcol0 = (PHASE == 1) ? (trans ? 256 : 128) : (trans ? 320 : 192);

    const __half* A  = g_adjh + (size_t)b * Nn * Nn;
    const __half* Zb = g_Zh + (size_t)b * Nn * DIN + XOFF;   // B rows, stride DIN
    const float* dinv = (trans ? g_dinv1 : g_dinv0);

    __shared__ __align__(16) __half As[STAGES * ASZ];
    __shared__ __align__(16) __half Bs[STAGES * BSZ];
    const unsigned as_u32 = (unsigned)__cvta_generic_to_shared(As);
    const unsigned bs_u32 = (unsigned)__cvta_generic_to_shared(Bs);

    const int tid  = threadIdx.x;
    const int w    = tid >> 5;
    const int lane = tid & 31;
    const int g4   = lane >> 2;
    const int t4   = lane & 3;
    const int warp_m = (w % wm_) * (BM / wm_);
    const int warp_n = (w / wm_) * (BN / wn_);

    // ldmatrix lane offsets (halfs)
    const int nt_off = ((lane & 7) + ((lane >> 3) & 1) * 8) * 24 + (lane >> 4) * 8;   // [m][24]
    const int tA_off = ((lane & 7) + ((lane >> 4) & 1) * 8) * 136 + ((lane >> 3) & 1) * 8; // [k][136]
    const int bB_off = ((lane & 7) + ((lane >> 3) & 1) * 8) * BSTR + (lane >> 4) * 8; // [k][BSTR]

    float acc[mf_][nf_][4];
    #pragma unroll
    for (int i = 0; i < mf_; i++)
        #pragma unroll
        for (int j = 0; j < nf_; j++)
            #pragma unroll
            for (int r = 0; r < 4; r++) acc[i][j][r] = 0.0f;

    auto issue1 = [&](int st, int k0) {
        __half* as = As + st * ASZ;
        __half* bs = Bs + st * BSZ;
        if (!trans) {   // 128 rows x 16 halfs (32B = 2 segments)
            int r = tid >> 1, seg = (tid & 1) * 8;
            cpasync16(&as[r * 24 + seg], &A[(size_t)(m0 + r) * Nn + k0 + seg]);
        } else {        // 16 rows x 128 halfs (16 segments)
            int k = tid >> 4, c = (tid & 15) * 8;
            cpasync16(&as[k * 136 + c], &A[(size_t)(k0 + k) * Nn + m0 + c]);
        }
        if (BN == 128) {
            int k = tid >> 4, c = (tid & 15) * 8;
            cpasync16(&bs[k * BSTR + c], &Zb[(size_t)(k0 + k) * DIN + c]);
        } else if (tid < 128) {
            int k = tid >> 3, c = (tid & 7) * 8;
            cpasync16(&bs[k * BSTR + c], &Zb[(size_t)(k0 + k) * DIN + c]);
        }
    };
    auto issuePair = [&](int pair, int k0) {
        issue1((pair & 1) * 2,     k0);
        issue1((pair & 1) * 2 + 1, k0 + BK);
        cp_commit();
    };

    constexpr int NP = Nn / (2 * BK);   // 32 pairs
    issuePair(0, 0);
    issuePair(1, 2 * BK);

    for (int t = 0; t < NP; t++) {
        cp_wait<1>();
        __syncthreads();
        #pragma unroll
        for (int sub = 0; sub < 2; sub++) {
            const int st = (t & 1) * 2 + sub;
            const unsigned asb = as_u32 + (st * ASZ) * 2;
            const unsigned bsb = bs_u32 + (st * BSZ) * 2;

            unsigned a[mf_][4];
            #pragma unroll
            for (int mf = 0; mf < mf_; mf++) {
                int mb = warp_m + mf * 16;
                if (!trans) ldsm4 (a[mf][0], a[mf][1], a[mf][2], a[mf][3],
                                   asb + (mb * 24 + nt_off) * 2);
                else        ldsm4t(a[mf][0], a[mf][1], a[mf][2], a[mf][3],
                                   asb + (mb + tA_off) * 2);
            }
            unsigned bf[nf_][2];
            #pragma unroll
            for (int nfp = 0; nfp < nf_ / 2; nfp++) {
                unsigned r0, r1, r2, r3;
                ldsm4t(r0, r1, r2, r3, bsb + (warp_n + nfp * 16 + bB_off) * 2);
                bf[2*nfp][0] = r0; bf[2*nfp][1] = r1;
                bf[2*nfp+1][0] = r2; bf[2*nfp+1][1] = r3;
            }
            #pragma unroll
            for (int nf = 0; nf < nf_; nf++)
                #pragma unroll
                for (int mf = 0; mf < mf_; mf++)
                    mma_f16(acc[mf][nf], a[mf][0], a[mf][1], a[mf][2], a[mf][3],
                            bf[nf][0], bf[nf][1]);
        }
        if (t + 2 < NP) issuePair(t + 2, (t + 2) * 2 * BK);
        else cp_commit();
    }

    // epilogue: Zh[row, zcol0+col] = rn_fp16(dinv[row]*(acc + Zchunk0[row, XOFF+col]))
    #pragma unroll
    for (int mf = 0; mf < mf_; mf++) {
        #pragma unroll
        for (int half = 0; half < 2; half++) {
            int rloc = warp_m + mf * 16 + g4 + half * 8;
            int rglob = b * Nn + m0 + rloc;
            float d = dinv[rglob];
            #pragma unroll
            for (int nf = 0; nf < nf_; nf++) {
                int cc = warp_n + nf * 8 + 2 * t4;
                __half2 xh = *reinterpret_cast<const __half2*>(
                    &g_Zh[(size_t)rglob * DIN + XOFF + cc]);
                float2 x = __half22float2(xh);
                float v0 = d * (acc[mf][nf][half * 2 + 0] + x.x);
                float v1 = d * (acc[mf][nf][half * 2 + 1] + x.y);
                *reinterpret_cast<__half2*>(&g_Zh[(size_t)rglob * DIN + zcol0 + cc]) =
                    __floats2half2_rn(v0, v1);
            }
        }
    }
}

// ------------------------------ weight GEMMs (fp16 mma) --------------------
// A = Zh rows [m][k] (stride 24); B = W [n][k] (stride 24, plain ldmatrix).
// WHICH=1: sigmoid(Z @ W1^T + b1s) -> Zh[:,64:128]=r*h, Ug.
// WHICH=2: tanh(Z @ Wc^T + bcs) -> out = u*h + (1-u)*c.
template <int WHICH>
__global__ __launch_bounds__(256) void k_wgemm(const float* __restrict__ hx,
                                               float* __restrict__ out) {
    constexpr int BN = (WHICH == 1) ? DU : Uu;
    constexpr int BM = 128, BK = 16, STAGES = 3;
    constexpr int ASZ = BM * 24;
    constexpr int WSZ = BN * 24;
    constexpr int wn_ = (BN == 128) ? 4 : 2;
    constexpr int wm_ = 8 / wn_;
    constexpr int mf_ = (BM / wm_) / 16;
    constexpr int nf_ = (BN / wn_) / 8;

    const int m0 = blockIdx.x * BM;
    const __half* Wc = (WHICH == 1) ? g_W1h : g_Wch;

    __shared__ __align__(16) __half As[STAGES * ASZ];
    __shared__ __align__(16) __half Ws[STAGES * WSZ];
    const unsigned as_u32 = (unsigned)__cvta_generic_to_shared(As);
    const unsigned ws_u32 = (unsigned)__cvta_generic_to_shared(Ws);

    const int tid  = threadIdx.x;
    const int w    = tid >> 5;
    const int lane = tid & 31;
    const int g4   = lane >> 2;
    const int t4   = lane & 3;
    const int warp_m = (w % wm_) * (BM / wm_);
    const int warp_n = (w / wm_) * (BN / wn_);

    const int nt_off = ((lane & 7) + ((lane >> 3) & 1) * 8) * 24 + (lane >> 4) * 8; // A [m][24]
    const int wB_off = ((lane & 7) + (lane >> 4) * 8) * 24 + ((lane >> 3) & 1) * 8; // W [n][24]

    float acc[mf_][nf_][4];
    #pragma unroll
    for (int i = 0; i < mf_; i++)
        #pragma unroll
        for (int j = 0; j < nf_; j++)
            #pragma unroll
            for (int r = 0; r < 4; r++) acc[i][j][r] = 0.0f;

    auto issue = [&](int st, int k0) {
        __half* as = As + st * ASZ;
        __half* ws = Ws + st * WSZ;
        {
            int r = tid >> 1, seg = (tid & 1) * 8;
            cpasync16(&as[r * 24 + seg], &g_Zh[(size_t)(m0 + r) * DIN + k0 + seg]);
        }
        if (BN == 128) {
            int n = tid >> 1, seg = (tid & 1) * 8;
            cpasync16(&ws[n * 24 + seg], &Wc[n * DIN + k0 + seg]);
        } else if (tid < 128) {
            int n = tid >> 1, seg = (tid & 1) * 8;
            cpasync16(&ws[n * 24 + seg], &Wc[n * DIN + k0 + seg]);
        }
        cp_commit();
    };

    constexpr int NT = DIN / BK;   // 24
    issue(0, 0); issue(1, BK);

    int st = 0;
    for (int kt = 0; kt < NT; kt++) {
        cp_wait<STAGES - 2>();
        __syncthreads();
        const unsigned asb = as_u32 + (st * ASZ) * 2;
        const unsigned wsb = ws_u32 + (st * WSZ) * 2;

        unsigned a[mf_][4];
        #pragma unroll
        for (int mf = 0; mf < mf_; mf++)
            ldsm4(a[mf][0], a[mf][1], a[mf][2], a[mf][3],
                  asb + ((warp_m + mf * 16) * 24 + nt_off) * 2);
        unsigned bf[nf_][2];
        #pragma unroll
        for (int nfp = 0; nfp < nf_ / 2; nfp++) {
            unsigned r0, r1, r2, r3;
            ldsm4(r0, r1, r2, r3, wsb + ((warp_n + nfp * 16) * 24 + wB_off) * 2);
            bf[2*nfp][0] = r0; bf[2*nfp][1] = r1;
            bf[2*nfp+1][0] = r2; bf[2*nfp+1][1] = r3;
        }
        #pragma unroll
        for (int nf = 0; nf < nf_; nf++)
            #pragma unroll
            for (int mf = 0; mf < mf_; mf++)
                mma_f16(acc[mf][nf], a[mf][0], a[mf][1], a[mf][2], a[mf][3],
                        bf[nf][0], bf[nf][1]);

        if (kt + STAGES - 1 < NT) issue((kt + STAGES - 1) % STAGES, (kt + STAGES - 1) * BK);
        else cp_commit();
        st = (st + 1 == STAGES) ? 0 : st + 1;
    }

    #pragma unroll
    for (int mf = 0; mf < mf_; mf++) {
        #pragma unroll
        for (int nf = 0; nf < nf_; nf++) {
            #pragma unroll
            for (int half = 0; half < 2; half++) {
                int row = m0 + warp_m + mf * 16 + g4 + half * 8;
                int o0 = warp_n + nf * 8 + 2 * t4;
                float v0 = acc[mf][nf][half * 2 + 0];
                float v1 = acc[mf][nf][half * 2 + 1];
                if (WHICH == 1) {
                    float val0 = sigm(v0 + g_b1s[o0]);
                    float val1 = sigm(v1 + g_b1s[o0 + 1]);
                    if (o0 < Uu) {
                        float rh0 = val0 * hx[row * Uu + o0];
                        float rh1 = val1 * hx[row * Uu + o0 + 1];
                        *reinterpret_cast<__half2*>(&g_Zh[(size_t)row * DIN + Uu + o0]) =
                            __floats2half2_rn(rh0, rh1);
                    } else {
                        g_Ug[row * Uu + o0 - Uu]     = val0;
                        g_Ug[row * Uu + o0 - Uu + 1] = val1;
                    }
                } else {
                    float c0 = tanhf(v0 + g_bcs[o0]);
                    float c1 = tanhf(v1 + g_bcs[o0 + 1]);
                    float u0 = g_Ug[row * Uu + o0], u1 = g_Ug[row * Uu + o0 + 1];
                    float h0 = hx[row * Uu + o0],   h1 = hx[row * Uu + o0 + 1];
                    out[row * Uu + o0]     = u0 * h0 + (1.0f - u0) * c0;
                    out[row * Uu + o0 + 1] = u1 * h1 + (1.0f - u1) * c1;
                }
            }
        }
    }
}

// ------------------------------ launch -------------------------------------
extern "C" void kernel_launch(void* const* d_in, const int* in_sizes, int n_in,
                              void* d_out, int out_size) {
    (void)in_sizes; (void)n_in; (void)out_size;
    const float* logits = (const float*)d_in[0];
    const float* u_noise = (const float*)d_in[1];
    const float* inputs = (const float*)d_in[2];
    const float* hx = (const float*)d_in[3];
    const float* W0 = (const float*)d_in[4];
    const float* b0 = (const float*)d_in[5];
    const float* W1 = (const float*)d_in[6];
    const float* b1 = (const float*)d_in[7];
    const float* Wc0 = (const float*)d_in[8];
    const float* bc0 = (const float*)d_in[9];
    const float* Wc1 = (const float*)d_in[10];
    const float* bc1 = (const float*)d_in[11];
    float* out = (float*)d_out;

    k_prep<<<64, 256>>>(W0, b0, W1, b1, Wc0, bc0, Wc1, bc1);
    k_adj<<<dim3(Nn, Bb), 256>>>((const float4*)logits, (const float4*)u_noise);
    k_colsum_part<<<dim3(Nn / 256, Bb, 4), 256>>>();
    k_buildZ0<<<(Mrows * 16) / 256, 256>>>(inputs, hx);
    k_gemm_tc<1><<<dim3(Nn / 128, 2, Bb), 256>>>();
    k_wgemm<1><<<Mrows / 128, 256>>>(hx, out);
    k_gemm_tc<2><<<dim3(Nn / 128, 2, Bb), 256>>>();
    k_wgemm<2><<<Mrows / 128, 256>>>(hx, out);
}